// round 14
// baseline (speedup 1.0000x reference)
#include <cuda_runtime.h>
#include <cuda_fp16.h>

#define HH 256
#define WW 256
#define BATCH 8
#define HW 65536

typedef unsigned long long ull;

// Scratch (allocation-free rule: __device__ globals)
__device__ float g_x[BATCH * 16 * HW];           // in_conv output  (33.5 MB)
__device__ __half g_xs[4 * BATCH * 16 * HW];     // dwconv outputs  (67 MB, fp16)
__device__ __half g_si[16 * BATCH * HW];         // per-channel SiLU*fw  (16.7 MB)

// ---------------- packed f32x2 helpers (sm_100+) ----------------
__device__ __forceinline__ ull pk2(float lo, float hi) {
    ull r;
    asm("mov.b64 %0, {%1, %2};" : "=l"(r) : "r"(__float_as_uint(lo)), "r"(__float_as_uint(hi)));
    return r;
}
__device__ __forceinline__ ull fma2(ull a, ull b, ull c) {
    ull d; asm("fma.rn.f32x2 %0, %1, %2, %3;" : "=l"(d) : "l"(a), "l"(b), "l"(c)); return d;
}

// ---------------------------------------------------------------------------
// K1: 1x1 in_conv 64 -> 16, packed f32x2 FFMA2 (2 px / thread)  [proven]
// ---------------------------------------------------------------------------
__global__ __launch_bounds__(256, 3) void k_inconv(const ull* __restrict__ cen2,
                                                   const float* __restrict__ w,
                                                   const float* __restrict__ bias) {
    __shared__ ull sw[1024];     // {w,w} packed
    __shared__ ull sb[16];
    for (int i = threadIdx.x; i < 1024; i += 256) { float v = w[i]; sw[i] = pk2(v, v); }
    if (threadIdx.x < 16) { float v = bias[threadIdx.x]; sb[threadIdx.x] = pk2(v, v); }
    __syncthreads();

    int idx = blockIdx.x * 256 + threadIdx.x;   // 0 .. 262143  (b, p2)
    int b = idx >> 15;
    int p2 = idx & 32767;
    const ull* cp = cen2 + (size_t)(b * 64) * 32768 + p2;

    ull acc[16];
#pragma unroll
    for (int o = 0; o < 16; o++) acc[o] = sb[o];

#pragma unroll 8
    for (int i = 0; i < 64; i++) {
        ull v = __ldg(cp + (size_t)i * 32768);
#pragma unroll
        for (int o = 0; o < 16; o++) acc[o] = fma2(v, sw[o * 64 + i], acc[o]);
    }
    ull* xp = reinterpret_cast<ull*>(g_x) + (size_t)(b * 16) * 32768 + p2;
#pragma unroll
    for (int o = 0; o < 16; o++) xp[(size_t)o * 32768] = acc[o];
}

// ---------------------------------------------------------------------------
// K2 (channel-parallel): one block = one (b, c), tile 32x32, 256 threads,
// 4-px x-run per thread for all 4 kernel sizes, ONE barrier, fp16 outputs.
// [R12, proven]
// ---------------------------------------------------------------------------
template <int S>
__device__ __forceinline__ void dwrun4(const float* __restrict__ st, int ty, int xr,
                                       const float* __restrict__ wk, float bias,
                                       float o[4]) {
    constexpr int P = S / 2;
    o[0] = bias; o[1] = bias; o[2] = bias; o[3] = bias;
#pragma unroll
    for (int kh = 0; kh < S; kh++) {
        const float* row = st + (ty + 3 - P + kh) * 39 + (xr + 3 - P);
        float v[S + 3];
#pragma unroll
        for (int j = 0; j < S + 3; j++) v[j] = row[j];
#pragma unroll
        for (int kw = 0; kw < S; kw++) {
            float wv = wk[kh * S + kw];
            o[0] = fmaf(wv, v[kw + 0], o[0]);
            o[1] = fmaf(wv, v[kw + 1], o[1]);
            o[2] = fmaf(wv, v[kw + 2], o[2]);
            o[3] = fmaf(wv, v[kw + 3], o[3]);
        }
    }
}

__global__ __launch_bounds__(256) void k_dw(
    const float* __restrict__ w1, const float* __restrict__ b1,
    const float* __restrict__ w3, const float* __restrict__ b3,
    const float* __restrict__ w5, const float* __restrict__ b5,
    const float* __restrict__ w7, const float* __restrict__ b7) {
    __shared__ float st[38 * 39];    // 32x32 tile + halo 3, stride 39
    __shared__ float sdw[84];        // this channel's weights: w1@0,w3@1,w5@10,w7@35
    __shared__ float sdb[4];

    int tid = threadIdx.x;
    int bc = blockIdx.z;             // b*16 + c
    int b = bc >> 4, c = bc & 15;
    int y0 = blockIdx.y * 32, x0 = blockIdx.x * 32;

    if (tid == 0)  sdw[0] = __ldg(w1 + c);
    else if (tid < 10)  sdw[tid] = __ldg(w3 + c * 9  + tid - 1);
    else if (tid < 35)  sdw[tid] = __ldg(w5 + c * 25 + tid - 10);
    else if (tid < 84)  sdw[tid] = __ldg(w7 + c * 49 + tid - 35);
    else if (tid < 88) {
        const float* bp[4] = {b1, b3, b5, b7};
        sdb[tid - 84] = __ldg(bp[tid - 84] + c);
    }

    const float* src = g_x + (size_t)(b * 16 + c) * HW;
#pragma unroll
    for (int j = 0; j < 6; j++) {
        int i = tid + j * 256;
        if (i < 38 * 38) {
            int r = i / 38, cl = i % 38;
            int gy = y0 - 3 + r, gx = x0 - 3 + cl;
            float v = 0.f;
            if ((unsigned)gy < 256u && (unsigned)gx < 256u)
                v = __ldg(src + gy * 256 + gx);
            st[r * 39 + cl] = v;
        }
    }
    __syncthreads();

    int ty = tid >> 3;               // 0..31
    int xr = (tid & 7) * 4;          // 0,4,..,28
    size_t pix = (size_t)((b * 16 + c)) * HW + (size_t)(y0 + ty) * 256 + (x0 + xr);

    float o[4];
    dwrun4<1>(st, ty, xr, sdw + 0, sdb[0], o);
    {
        __half2* dst = reinterpret_cast<__half2*>(g_xs + (size_t)0 * BATCH * 16 * HW + pix);
        dst[0] = __halves2half2(__float2half_rn(o[0]), __float2half_rn(o[1]));
        dst[1] = __halves2half2(__float2half_rn(o[2]), __float2half_rn(o[3]));
    }
    dwrun4<3>(st, ty, xr, sdw + 1, sdb[1], o);
    {
        __half2* dst = reinterpret_cast<__half2*>(g_xs + (size_t)1 * BATCH * 16 * HW + pix);
        dst[0] = __halves2half2(__float2half_rn(o[0]), __float2half_rn(o[1]));
        dst[1] = __halves2half2(__float2half_rn(o[2]), __float2half_rn(o[3]));
    }
    dwrun4<5>(st, ty, xr, sdw + 10, sdb[2], o);
    {
        __half2* dst = reinterpret_cast<__half2*>(g_xs + (size_t)2 * BATCH * 16 * HW + pix);
        dst[0] = __halves2half2(__float2half_rn(o[0]), __float2half_rn(o[1]));
        dst[1] = __halves2half2(__float2half_rn(o[2]), __float2half_rn(o[3]));
    }
    dwrun4<7>(st, ty, xr, sdw + 35, sdb[3], o);
    {
        __half2* dst = reinterpret_cast<__half2*>(g_xs + (size_t)3 * BATCH * 16 * HW + pix);
        dst[0] = __halves2half2(__float2half_rn(o[0]), __float2half_rn(o[1]));
        dst[1] = __halves2half2(__float2half_rn(o[2]), __float2half_rn(o[3]));
    }
}

// ---------------------------------------------------------------------------
// K3 (channel-parallel): one block = one (b, c, 32x16 tile). Stage 4 fp16
// regions -> fp32 smem, ONE barrier, branch math + sort8 + sort4 + BN + SiLU,
// write si*fw[c] to g_si (fp16).  No channel loop.
// ---------------------------------------------------------------------------
__device__ __forceinline__ void ce(float& a, float& b) {
    float lo = fminf(a, b);
    float hi = fmaxf(a, b);
    a = lo; b = hi;
}

template <int S, int C>
__device__ __forceinline__ float branch_val(const float* __restrict__ sx, int ty,
                                            int tx, const float* __restrict__ wB) {
    const float* ctr = sx + (ty + S) * C + (tx + S);
    float xc = ctr[0];
    float T[8];
    T[0] = xc - ctr[-S * C - S];
    T[1] = xc - ctr[-S * C];
    T[2] = xc - ctr[-S * C + S];
    T[3] = xc - ctr[S];
    T[4] = xc - ctr[S * C + S];
    T[5] = xc - ctr[S * C];
    T[6] = xc - ctr[S * C - S];
    T[7] = xc - ctr[-S];
    float Sv[4];
#pragma unroll
    for (int k = 0; k < 4; k++) Sv[k] = T[k] + T[k + 4];

    float w10 = wB[0], w11 = wB[1], w12 = wB[2], w13x2 = wB[3], b1 = wB[4];
    float base[4];
#pragma unroll
    for (int j = 0; j < 4; j++) {
        float o = fmaf(w10, Sv[(j + 1) & 3], b1);
        o = fmaf(w11, Sv[(j + 3) & 3], o);
        base[j] = fmaf(w12, Sv[(j + 2) & 3], o);
    }
    float v[8];
#pragma unroll
    for (int k = 0; k < 8; k++)
        v[k] = fmaf(w13x2, T[(k + 4) & 7], base[k & 3]) * T[k];  // wB[3] pre-doubled

    ce(v[0], v[1]); ce(v[2], v[3]); ce(v[0], v[2]); ce(v[1], v[3]); ce(v[1], v[2]);
    ce(v[4], v[5]); ce(v[6], v[7]); ce(v[4], v[6]); ce(v[5], v[7]); ce(v[5], v[6]);
    ce(v[0], v[4]); ce(v[1], v[5]); ce(v[2], v[6]); ce(v[3], v[7]);
    ce(v[2], v[4]); ce(v[3], v[5]);
    ce(v[1], v[2]); ce(v[3], v[4]); ce(v[5], v[6]);

    float r = wB[13];
#pragma unroll
    for (int j = 0; j < 8; j++) r = fmaf(v[j], wB[5 + j], r);
    return r;
}

template <int S>
__device__ __forceinline__ void stage_region(float* __restrict__ dst,
                                             const __half* __restrict__ src,
                                             int y0, int x0, int tid) {
    constexpr int R = 16 + 2 * S, C = 32 + 2 * S;
#pragma unroll 1
    for (int i = tid; i < R * C; i += 256) {
        int rr = i / C, cl = i % C;
        int gy = y0 - S + rr, gx = x0 - S + cl;
        float v = 0.f;
        if ((unsigned)gy < 256u && (unsigned)gx < 256u)
            v = __half2float(__ldg(src + gy * 256 + gx));
        dst[i] = v;
    }
}

__global__ __launch_bounds__(256) void k_main(
    const float* __restrict__ l1_w, const float* __restrict__ l1_b,
    const float* __restrict__ l2_w, const float* __restrict__ l2_b,
    const float* __restrict__ base_w, const float* __restrict__ bn_scale,
    const float* __restrict__ bn_bias, const float* __restrict__ final_w) {
    // Regions for 32x16 tile: S=1: 18x34=612 @0; S=3: 22x38=836 @612;
    // S=5: 26x42=1092 @1448; S=7: 30x46=1380 @2540; total 3920
    __shared__ float sxt[3920];
    __shared__ float swB[4 * 14];    // this channel: per branch w1[4](e3 dbl),b1,w2[8],b2
    __shared__ float sbase[4];
    __shared__ float sEps[3];        // bnS, bnB, fw

    int tid = threadIdx.x;
    int bc = blockIdx.z;             // b*16 + c
    int b = bc >> 4, c = bc & 15;
    int x0 = blockIdx.x * 32, y0 = blockIdx.y * 16;

    if (tid < 56) {
        int br = tid / 14, e = tid % 14;
        float v;
        if (e < 4) { v = __ldg(l1_w + (br * 16 + c) * 4 + e); if (e == 3) v *= 2.f; }
        else if (e == 4) v = __ldg(l1_b + br * 16 + c);
        else if (e < 13) v = __ldg(l2_w + (br * 16 + c) * 8 + (e - 5));
        else v = __ldg(l2_b + br * 16 + c);
        swB[tid] = v;
    } else if (tid < 60) {
        sbase[tid - 56] = __ldg(base_w + c * 4 + (tid - 56));
    } else if (tid == 60) sEps[0] = __ldg(bn_scale + c);
    else if (tid == 61) sEps[1] = __ldg(bn_bias + c);
    else if (tid == 62) sEps[2] = __ldg(final_w + c);

    size_t coff = (size_t)(b * 16 + c) * HW;
    stage_region<1>(sxt + 0,    g_xs + (size_t)0 * BATCH * 16 * HW + coff, y0, x0, tid);
    stage_region<3>(sxt + 612,  g_xs + (size_t)1 * BATCH * 16 * HW + coff, y0, x0, tid);
    stage_region<5>(sxt + 1448, g_xs + (size_t)2 * BATCH * 16 * HW + coff, y0, x0, tid);
    stage_region<7>(sxt + 2540, g_xs + (size_t)3 * BATCH * 16 * HW + coff, y0, x0, tid);
    __syncthreads();

    int tx = tid & 31, ty = tid >> 5;      // ty 0..7; px (ty,tx) and (ty+8,tx)
    float bnS = sEps[0], bnB = sEps[1], fw = sEps[2];

    __half2 res[1];
#pragma unroll
    for (int h = 0; h < 2; h++) {
        int py = ty + h * 8;
        float bv0 = branch_val<1, 34>(sxt + 0,    py, tx, swB + 0 * 14);
        float bv1 = branch_val<3, 38>(sxt + 612,  py, tx, swB + 1 * 14);
        float bv2 = branch_val<5, 42>(sxt + 1448, py, tx, swB + 2 * 14);
        float bv3 = branch_val<7, 46>(sxt + 2540, py, tx, swB + 3 * 14);

        ce(bv0, bv1); ce(bv2, bv3); ce(bv0, bv2); ce(bv1, bv3); ce(bv1, bv2);

        float y = bv0 * sbase[0];
        y = fmaf(bv1, sbase[1], y);
        y = fmaf(bv2, sbase[2], y);
        y = fmaf(bv3, sbase[3], y);
        float t = fmaf(y, bnS, bnB);
        float si = __fdividef(t, 1.f + __expf(-t)) * fw;
        g_si[(size_t)(c * BATCH + b) * HW + (size_t)(y0 + py) * 256 + (x0 + tx)] =
            __float2half_rn(si);
    }
    (void)res;
}

// ---------------------------------------------------------------------------
// K4: reduce 16 channels + final bias + sigmoid.  4 px / thread, ull loads.
// ---------------------------------------------------------------------------
__global__ __launch_bounds__(256) void k_reduce(const float* __restrict__ final_b,
                                                float* __restrict__ out) {
    int idx = blockIdx.x * 256 + threadIdx.x;   // 0..131071: (b, p4)
    int b = idx >> 14;
    int p4 = idx & 16383;
    float fb = __ldg(final_b);
    float a0 = fb, a1 = fb, a2 = fb, a3 = fb;

    const ull* base = reinterpret_cast<const ull*>(g_si) + (size_t)b * 16384 + p4;
#pragma unroll
    for (int c = 0; c < 16; c++) {
        ull v = __ldg(base + (size_t)c * BATCH * 16384);
        unsigned lo = (unsigned)v, hi = (unsigned)(v >> 32);
        float2 f0 = __half22float2(*reinterpret_cast<__half2*>(&lo));
        float2 f1 = __half22float2(*reinterpret_cast<__half2*>(&hi));
        a0 += f0.x; a1 += f0.y; a2 += f1.x; a3 += f1.y;
    }
    float4 o;
    o.x = __fdividef(1.f, 1.f + __expf(-a0));
    o.y = __fdividef(1.f, 1.f + __expf(-a1));
    o.z = __fdividef(1.f, 1.f + __expf(-a2));
    o.w = __fdividef(1.f, 1.f + __expf(-a3));
    reinterpret_cast<float4*>(out)[(size_t)b * 16384 + p4] = o;
}

// ---------------------------------------------------------------------------
extern "C" void kernel_launch(void* const* d_in, const int* in_sizes, int n_in,
                              void* d_out, int out_size) {
    (void)in_sizes; (void)n_in; (void)out_size;
    const ull* cen = (const ull*)d_in[0];
    // d_in[1] = mas (unused by the reference computation)
    const float* in_w = (const float*)d_in[2];
    const float* in_b = (const float*)d_in[3];

    k_inconv<<<1024, 256>>>(cen, in_w, in_b);

    dim3 g2(8, 8, 128);   // W/32, H/32, B*C
    k_dw<<<g2, 256>>>((const float*)d_in[4],  (const float*)d_in[5],
                      (const float*)d_in[6],  (const float*)d_in[7],
                      (const float*)d_in[8],  (const float*)d_in[9],
                      (const float*)d_in[10], (const float*)d_in[11]);

    dim3 g3(8, 16, 128);  // W/32, H/16, B*C
    k_main<<<g3, 256>>>((const float*)d_in[12], (const float*)d_in[13],
                        (const float*)d_in[14], (const float*)d_in[15],
                        (const float*)d_in[16], (const float*)d_in[17],
                        (const float*)d_in[18], (const float*)d_in[19]);

    k_reduce<<<512, 256>>>((const float*)d_in[20], (float*)d_out);
}

// round 15
// speedup vs baseline: 1.3729x; 1.3729x over previous
#include <cuda_runtime.h>
#include <cuda_fp16.h>

#define HH 256
#define WW 256
#define BATCH 8
#define HW 65536

typedef unsigned long long ull;

// Scratch (allocation-free rule: __device__ globals)
__device__ __half g_x[BATCH * 16 * HW];          // in_conv output  (16.7 MB, fp16)
__device__ __half g_xs[4 * BATCH * 16 * HW];     // dwconv outputs  (67 MB, fp16)

// ---------------- packed f32x2 helpers (sm_100+) ----------------
__device__ __forceinline__ ull pk2(float lo, float hi) {
    ull r;
    asm("mov.b64 %0, {%1, %2};" : "=l"(r) : "r"(__float_as_uint(lo)), "r"(__float_as_uint(hi)));
    return r;
}
__device__ __forceinline__ void upk2(ull v, float& lo, float& hi) {
    unsigned a, b;
    asm("mov.b64 {%0, %1}, %2;" : "=r"(a), "=r"(b) : "l"(v));
    lo = __uint_as_float(a); hi = __uint_as_float(b);
}
__device__ __forceinline__ ull fma2(ull a, ull b, ull c) {
    ull d; asm("fma.rn.f32x2 %0, %1, %2, %3;" : "=l"(d) : "l"(a), "l"(b), "l"(c)); return d;
}

// ---------------------------------------------------------------------------
// K1: 1x1 in_conv 64 -> 16, packed f32x2 FFMA2 (2 px / thread), fp16 out
// ---------------------------------------------------------------------------
__global__ __launch_bounds__(256, 3) void k_inconv(const ull* __restrict__ cen2,
                                                   const float* __restrict__ w,
                                                   const float* __restrict__ bias) {
    __shared__ ull sw[1024];     // {w,w} packed
    __shared__ ull sb[16];
    for (int i = threadIdx.x; i < 1024; i += 256) { float v = w[i]; sw[i] = pk2(v, v); }
    if (threadIdx.x < 16) { float v = bias[threadIdx.x]; sb[threadIdx.x] = pk2(v, v); }
    __syncthreads();

    int idx = blockIdx.x * 256 + threadIdx.x;   // 0 .. 262143  (b, p2)
    int b = idx >> 15;
    int p2 = idx & 32767;
    const ull* cp = cen2 + (size_t)(b * 64) * 32768 + p2;

    ull acc[16];
#pragma unroll
    for (int o = 0; o < 16; o++) acc[o] = sb[o];

#pragma unroll 8
    for (int i = 0; i < 64; i++) {
        ull v = __ldg(cp + (size_t)i * 32768);
#pragma unroll
        for (int o = 0; o < 16; o++) acc[o] = fma2(v, sw[o * 64 + i], acc[o]);
    }
    __half2* xp = reinterpret_cast<__half2*>(g_x) + (size_t)(b * 16) * 32768 + p2;
#pragma unroll
    for (int o = 0; o < 16; o++) {
        float lo, hi; upk2(acc[o], lo, hi);
        xp[(size_t)o * 32768] = __halves2half2(__float2half_rn(lo), __float2half_rn(hi));
    }
}

// ---------------------------------------------------------------------------
// K2 (channel-parallel): one block = one (b, c), tile 32x32, 256 threads,
// 4-px x-run per thread for all 4 kernel sizes, ONE barrier, fp16 in/out.
// ---------------------------------------------------------------------------
template <int S>
__device__ __forceinline__ void dwrun4(const float* __restrict__ st, int ty, int xr,
                                       const float* __restrict__ wk, float bias,
                                       float o[4]) {
    constexpr int P = S / 2;
    o[0] = bias; o[1] = bias; o[2] = bias; o[3] = bias;
#pragma unroll
    for (int kh = 0; kh < S; kh++) {
        const float* row = st + (ty + 3 - P + kh) * 39 + (xr + 3 - P);
        float v[S + 3];
#pragma unroll
        for (int j = 0; j < S + 3; j++) v[j] = row[j];
#pragma unroll
        for (int kw = 0; kw < S; kw++) {
            float wv = wk[kh * S + kw];
            o[0] = fmaf(wv, v[kw + 0], o[0]);
            o[1] = fmaf(wv, v[kw + 1], o[1]);
            o[2] = fmaf(wv, v[kw + 2], o[2]);
            o[3] = fmaf(wv, v[kw + 3], o[3]);
        }
    }
}

__global__ __launch_bounds__(256) void k_dw(
    const float* __restrict__ w1, const float* __restrict__ b1,
    const float* __restrict__ w3, const float* __restrict__ b3,
    const float* __restrict__ w5, const float* __restrict__ b5,
    const float* __restrict__ w7, const float* __restrict__ b7) {
    __shared__ float st[38 * 39];    // 32x32 tile + halo 3, stride 39
    __shared__ float sdw[84];        // this channel's weights: w1@0,w3@1,w5@10,w7@35
    __shared__ float sdb[4];

    int tid = threadIdx.x;
    int bc = blockIdx.z;             // b*16 + c
    int b = bc >> 4, c = bc & 15;
    int y0 = blockIdx.y * 32, x0 = blockIdx.x * 32;

    if (tid == 0)  sdw[0] = __ldg(w1 + c);
    else if (tid < 10)  sdw[tid] = __ldg(w3 + c * 9  + tid - 1);
    else if (tid < 35)  sdw[tid] = __ldg(w5 + c * 25 + tid - 10);
    else if (tid < 84)  sdw[tid] = __ldg(w7 + c * 49 + tid - 35);
    else if (tid < 88) {
        const float* bp[4] = {b1, b3, b5, b7};
        sdb[tid - 84] = __ldg(bp[tid - 84] + c);
    }

    const __half* src = g_x + (size_t)(b * 16 + c) * HW;
#pragma unroll
    for (int j = 0; j < 6; j++) {
        int i = tid + j * 256;
        if (i < 38 * 38) {
            int r = i / 38, cl = i % 38;
            int gy = y0 - 3 + r, gx = x0 - 3 + cl;
            float v = 0.f;
            if ((unsigned)gy < 256u && (unsigned)gx < 256u)
                v = __half2float(__ldg(src + gy * 256 + gx));
            st[r * 39 + cl] = v;
        }
    }
    __syncthreads();

    int ty = tid >> 3;               // 0..31
    int xr = (tid & 7) * 4;          // 0,4,..,28
    size_t pix = (size_t)((b * 16 + c)) * HW + (size_t)(y0 + ty) * 256 + (x0 + xr);

    float o[4];
    dwrun4<1>(st, ty, xr, sdw + 0, sdb[0], o);
    {
        __half2* dst = reinterpret_cast<__half2*>(g_xs + (size_t)0 * BATCH * 16 * HW + pix);
        dst[0] = __halves2half2(__float2half_rn(o[0]), __float2half_rn(o[1]));
        dst[1] = __halves2half2(__float2half_rn(o[2]), __float2half_rn(o[3]));
    }
    dwrun4<3>(st, ty, xr, sdw + 1, sdb[1], o);
    {
        __half2* dst = reinterpret_cast<__half2*>(g_xs + (size_t)1 * BATCH * 16 * HW + pix);
        dst[0] = __halves2half2(__float2half_rn(o[0]), __float2half_rn(o[1]));
        dst[1] = __halves2half2(__float2half_rn(o[2]), __float2half_rn(o[3]));
    }
    dwrun4<5>(st, ty, xr, sdw + 10, sdb[2], o);
    {
        __half2* dst = reinterpret_cast<__half2*>(g_xs + (size_t)2 * BATCH * 16 * HW + pix);
        dst[0] = __halves2half2(__float2half_rn(o[0]), __float2half_rn(o[1]));
        dst[1] = __halves2half2(__float2half_rn(o[2]), __float2half_rn(o[3]));
    }
    dwrun4<7>(st, ty, xr, sdw + 35, sdb[3], o);
    {
        __half2* dst = reinterpret_cast<__half2*>(g_xs + (size_t)3 * BATCH * 16 * HW + pix);
        dst[0] = __halves2half2(__float2half_rn(o[0]), __float2half_rn(o[1]));
        dst[1] = __halves2half2(__float2half_rn(o[2]), __float2half_rn(o[3]));
    }
}

// ---------------------------------------------------------------------------
// K3: fused tail, tile 32x16, 512 threads, scalar fp32 math, channel
// register-prefetch pipeline (fp16 gmem -> fp32 smem).  [proven R10 version]
// ---------------------------------------------------------------------------
__device__ __forceinline__ void ce(float& a, float& b) {
    float lo = fminf(a, b);
    float hi = fmaxf(a, b);
    a = lo; b = hi;
}

template <int S, int C>
__device__ __forceinline__ float branch_val(const float* __restrict__ sx, int ty,
                                            int tx, const float* __restrict__ wB) {
    const float* ctr = sx + (ty + S) * C + (tx + S);
    float xc = ctr[0];
    float T[8];
    T[0] = xc - ctr[-S * C - S];
    T[1] = xc - ctr[-S * C];
    T[2] = xc - ctr[-S * C + S];
    T[3] = xc - ctr[S];
    T[4] = xc - ctr[S * C + S];
    T[5] = xc - ctr[S * C];
    T[6] = xc - ctr[S * C - S];
    T[7] = xc - ctr[-S];
    float Sv[4];
#pragma unroll
    for (int k = 0; k < 4; k++) Sv[k] = T[k] + T[k + 4];

    float w10 = wB[0], w11 = wB[1], w12 = wB[2], w13x2 = wB[3], b1 = wB[4];
    float base[4];
#pragma unroll
    for (int j = 0; j < 4; j++) {
        float o = fmaf(w10, Sv[(j + 1) & 3], b1);
        o = fmaf(w11, Sv[(j + 3) & 3], o);
        base[j] = fmaf(w12, Sv[(j + 2) & 3], o);
    }
    float v[8];
#pragma unroll
    for (int k = 0; k < 8; k++)
        v[k] = fmaf(w13x2, T[(k + 4) & 7], base[k & 3]) * T[k];  // wB[3] pre-doubled

    // Batcher odd-even mergesort, 8 elems, 19 CEs, ascending
    ce(v[0], v[1]); ce(v[2], v[3]); ce(v[0], v[2]); ce(v[1], v[3]); ce(v[1], v[2]);
    ce(v[4], v[5]); ce(v[6], v[7]); ce(v[4], v[6]); ce(v[5], v[7]); ce(v[5], v[6]);
    ce(v[0], v[4]); ce(v[1], v[5]); ce(v[2], v[6]); ce(v[3], v[7]);
    ce(v[2], v[4]); ce(v[3], v[5]);
    ce(v[1], v[2]); ce(v[3], v[4]); ce(v[5], v[6]);

    float r = wB[13];
#pragma unroll
    for (int j = 0; j < 8; j++) r = fmaf(v[j], wB[5 + j], r);
    return r;
}

template <int S, int NR>
__device__ __forceinline__ void m_prefetch(float r[NR], const __half* __restrict__ src,
                                           int y0, int x0, int tid) {
    constexpr int R = 16 + 2 * S, C = 32 + 2 * S;
#pragma unroll
    for (int j = 0; j < NR; j++) {
        int i = tid + j * 512;
        float v = 0.f;
        if (i < R * C) {
            int rr = i / C, cl = i % C;
            int gy = y0 - S + rr, gx = x0 - S + cl;
            if ((unsigned)gy < 256u && (unsigned)gx < 256u)
                v = __half2float(__ldg(src + gy * 256 + gx));
        }
        r[j] = v;
    }
}

template <int S, int NR>
__device__ __forceinline__ void m_commit(const float r[NR], float* __restrict__ dst,
                                         int tid) {
    constexpr int R = 16 + 2 * S, C = 32 + 2 * S;
#pragma unroll
    for (int j = 0; j < NR; j++) {
        int i = tid + j * 512;
        if (i < R * C) dst[i] = r[j];
    }
}

__global__ __launch_bounds__(512) void k_main(
    const float* __restrict__ l1_w, const float* __restrict__ l1_b,
    const float* __restrict__ l2_w, const float* __restrict__ l2_b,
    const float* __restrict__ base_w, const float* __restrict__ bn_scale,
    const float* __restrict__ bn_bias, const float* __restrict__ final_w,
    const float* __restrict__ final_b, float* __restrict__ out) {
    // Regions for 32x16 tile: S=1: 18x34=612 @0; S=3: 22x38=836 @612;
    // S=5: 26x42=1092 @1448; S=7: 30x46=1380 @2540; total 3920
    __shared__ float sxt[3920];
    __shared__ float swB[4 * 16 * 14];   // per branch/channel: w1[4],b1,w2[8],b2
    __shared__ float sbase[64];
    __shared__ float sbnS[16], sbnB[16], sfw[16];

    int tid = threadIdx.x;
    for (int i = tid; i < 896; i += 512) {
        int e = i % 14;
        int rest = i / 14;
        int cc = rest % 16, br = rest / 16;
        float v;
        if (e < 4) { v = l1_w[(br * 16 + cc) * 4 + e]; if (e == 3) v *= 2.f; }
        else if (e == 4) v = l1_b[br * 16 + cc];
        else if (e < 13) v = l2_w[(br * 16 + cc) * 8 + (e - 5)];
        else v = l2_b[br * 16 + cc];
        swB[i] = v;
    }
    if (tid < 64) sbase[tid] = base_w[tid];
    if (tid < 16) { sbnS[tid] = bn_scale[tid]; sbnB[tid] = bn_bias[tid]; sfw[tid] = final_w[tid]; }

    int tx = tid & 31, ty = tid >> 5;     // ty 0..15
    int x0 = blockIdx.x * 32, y0 = blockIdx.y * 16;
    int b = blockIdx.z;
    float acc = __ldg(final_b);

    const __half* s1 = g_xs + (size_t)((0 * BATCH + b) * 16) * HW;
    const __half* s3 = g_xs + (size_t)((1 * BATCH + b) * 16) * HW;
    const __half* s5 = g_xs + (size_t)((2 * BATCH + b) * 16) * HW;
    const __half* s7 = g_xs + (size_t)((3 * BATCH + b) * 16) * HW;

    float r1[2], r3[2], r5[3], r7[3];
    m_prefetch<1, 2>(r1, s1, y0, x0, tid);
    m_prefetch<3, 2>(r3, s3, y0, x0, tid);
    m_prefetch<5, 3>(r5, s5, y0, x0, tid);
    m_prefetch<7, 3>(r7, s7, y0, x0, tid);

#pragma unroll 1
    for (int c = 0; c < 16; c++) {
        __syncthreads();
        m_commit<1, 2>(r1, sxt + 0,    tid);
        m_commit<3, 2>(r3, sxt + 612,  tid);
        m_commit<5, 3>(r5, sxt + 1448, tid);
        m_commit<7, 3>(r7, sxt + 2540, tid);
        __syncthreads();
        if (c < 15) {
            size_t off = (size_t)(c + 1) * HW;
            m_prefetch<1, 2>(r1, s1 + off, y0, x0, tid);
            m_prefetch<3, 2>(r3, s3 + off, y0, x0, tid);
            m_prefetch<5, 3>(r5, s5 + off, y0, x0, tid);
            m_prefetch<7, 3>(r7, s7 + off, y0, x0, tid);
        }

        float bv0 = branch_val<1, 34>(sxt + 0,    ty, tx, swB + (0 * 16 + c) * 14);
        float bv1 = branch_val<3, 38>(sxt + 612,  ty, tx, swB + (1 * 16 + c) * 14);
        float bv2 = branch_val<5, 42>(sxt + 1448, ty, tx, swB + (2 * 16 + c) * 14);
        float bv3 = branch_val<7, 46>(sxt + 2540, ty, tx, swB + (3 * 16 + c) * 14);

        // sort4 ascending
        ce(bv0, bv1); ce(bv2, bv3); ce(bv0, bv2); ce(bv1, bv3); ce(bv1, bv2);

        float y = bv0 * sbase[c * 4 + 0];
        y = fmaf(bv1, sbase[c * 4 + 1], y);
        y = fmaf(bv2, sbase[c * 4 + 2], y);
        y = fmaf(bv3, sbase[c * 4 + 3], y);
        float t = fmaf(y, sbnS[c], sbnB[c]);
        float si = __fdividef(t, 1.f + __expf(-t));          // SiLU (fast)
        acc = fmaf(si, sfw[c], acc);
    }
    out[(size_t)b * HW + (size_t)(y0 + ty) * 256 + (x0 + tx)] =
        __fdividef(1.f, 1.f + __expf(-acc));
}

// ---------------------------------------------------------------------------
extern "C" void kernel_launch(void* const* d_in, const int* in_sizes, int n_in,
                              void* d_out, int out_size) {
    (void)in_sizes; (void)n_in; (void)out_size;
    const ull* cen = (const ull*)d_in[0];
    // d_in[1] = mas (unused by the reference computation)
    const float* in_w = (const float*)d_in[2];
    const float* in_b = (const float*)d_in[3];

    k_inconv<<<1024, 256>>>(cen, in_w, in_b);

    dim3 g2(8, 8, 128);   // W/32, H/32, B*C
    k_dw<<<g2, 256>>>((const float*)d_in[4],  (const float*)d_in[5],
                      (const float*)d_in[6],  (const float*)d_in[7],
                      (const float*)d_in[8],  (const float*)d_in[9],
                      (const float*)d_in[10], (const float*)d_in[11]);

    dim3 g3(8, 16, 8);   // W/32, H/16, B
    k_main<<<g3, 512>>>((const float*)d_in[12], (const float*)d_in[13],
                        (const float*)d_in[14], (const float*)d_in[15],
                        (const float*)d_in[16], (const float*)d_in[17],
                        (const float*)d_in[18], (const float*)d_in[19],
                        (const float*)d_in[20], (float*)d_out);
}

// round 16
// speedup vs baseline: 1.3778x; 1.0035x over previous
#include <cuda_runtime.h>
#include <cuda_fp16.h>

#define HH 256
#define WW 256
#define BATCH 8
#define HW 65536

typedef unsigned long long ull;

// Scratch (allocation-free rule: __device__ globals)
__device__ __half g_x[BATCH * 16 * HW];          // in_conv output  (16.7 MB, fp16)
__device__ __half g_xs[4 * BATCH * 16 * HW];     // dwconv outputs  (67 MB, fp16)

// ---------------- packed f32x2 helpers (sm_100+) ----------------
__device__ __forceinline__ ull pk2(float lo, float hi) {
    ull r;
    asm("mov.b64 %0, {%1, %2};" : "=l"(r) : "r"(__float_as_uint(lo)), "r"(__float_as_uint(hi)));
    return r;
}
__device__ __forceinline__ void upk2(ull v, float& lo, float& hi) {
    unsigned a, b;
    asm("mov.b64 {%0, %1}, %2;" : "=r"(a), "=r"(b) : "l"(v));
    lo = __uint_as_float(a); hi = __uint_as_float(b);
}
__device__ __forceinline__ ull fma2(ull a, ull b, ull c) {
    ull d; asm("fma.rn.f32x2 %0, %1, %2, %3;" : "=l"(d) : "l"(a), "l"(b), "l"(c)); return d;
}

// ---------------------------------------------------------------------------
// K1: 1x1 in_conv 64 -> 16, packed f32x2 FFMA2 (2 px / thread), fp16 out
// ---------------------------------------------------------------------------
__global__ __launch_bounds__(256, 3) void k_inconv(const ull* __restrict__ cen2,
                                                   const float* __restrict__ w,
                                                   const float* __restrict__ bias) {
    __shared__ ull sw[1024];     // {w,w} packed
    __shared__ ull sb[16];
    for (int i = threadIdx.x; i < 1024; i += 256) { float v = w[i]; sw[i] = pk2(v, v); }
    if (threadIdx.x < 16) { float v = bias[threadIdx.x]; sb[threadIdx.x] = pk2(v, v); }
    __syncthreads();

    int idx = blockIdx.x * 256 + threadIdx.x;   // 0 .. 262143  (b, p2)
    int b = idx >> 15;
    int p2 = idx & 32767;
    const ull* cp = cen2 + (size_t)(b * 64) * 32768 + p2;

    ull acc[16];
#pragma unroll
    for (int o = 0; o < 16; o++) acc[o] = sb[o];

#pragma unroll 8
    for (int i = 0; i < 64; i++) {
        ull v = __ldg(cp + (size_t)i * 32768);
#pragma unroll
        for (int o = 0; o < 16; o++) acc[o] = fma2(v, sw[o * 64 + i], acc[o]);
    }
    __half2* xp = reinterpret_cast<__half2*>(g_x) + (size_t)(b * 16) * 32768 + p2;
#pragma unroll
    for (int o = 0; o < 16; o++) {
        float lo, hi; upk2(acc[o], lo, hi);
        xp[(size_t)o * 32768] = __halves2half2(__float2half_rn(lo), __float2half_rn(hi));
    }
}

// ---------------------------------------------------------------------------
// K2 (channel-parallel): one block = one (b, c), tile 32x32, 256 threads,
// 4-px x-run per thread for all 4 kernel sizes, ONE barrier, fp16 in/out.
// ---------------------------------------------------------------------------
template <int S>
__device__ __forceinline__ void dwrun4(const float* __restrict__ st, int ty, int xr,
                                       const float* __restrict__ wk, float bias,
                                       float o[4]) {
    constexpr int P = S / 2;
    o[0] = bias; o[1] = bias; o[2] = bias; o[3] = bias;
#pragma unroll
    for (int kh = 0; kh < S; kh++) {
        const float* row = st + (ty + 3 - P + kh) * 39 + (xr + 3 - P);
        float v[S + 3];
#pragma unroll
        for (int j = 0; j < S + 3; j++) v[j] = row[j];
#pragma unroll
        for (int kw = 0; kw < S; kw++) {
            float wv = wk[kh * S + kw];
            o[0] = fmaf(wv, v[kw + 0], o[0]);
            o[1] = fmaf(wv, v[kw + 1], o[1]);
            o[2] = fmaf(wv, v[kw + 2], o[2]);
            o[3] = fmaf(wv, v[kw + 3], o[3]);
        }
    }
}

__global__ __launch_bounds__(256) void k_dw(
    const float* __restrict__ w1, const float* __restrict__ b1,
    const float* __restrict__ w3, const float* __restrict__ b3,
    const float* __restrict__ w5, const float* __restrict__ b5,
    const float* __restrict__ w7, const float* __restrict__ b7) {
    __shared__ float st[38 * 39];    // 32x32 tile + halo 3, stride 39
    __shared__ float sdw[84];        // this channel's weights: w1@0,w3@1,w5@10,w7@35
    __shared__ float sdb[4];

    int tid = threadIdx.x;
    int bc = blockIdx.z;             // b*16 + c
    int b = bc >> 4, c = bc & 15;
    int y0 = blockIdx.y * 32, x0 = blockIdx.x * 32;

    if (tid == 0)  sdw[0] = __ldg(w1 + c);
    else if (tid < 10)  sdw[tid] = __ldg(w3 + c * 9  + tid - 1);
    else if (tid < 35)  sdw[tid] = __ldg(w5 + c * 25 + tid - 10);
    else if (tid < 84)  sdw[tid] = __ldg(w7 + c * 49 + tid - 35);
    else if (tid < 88) {
        const float* bp[4] = {b1, b3, b5, b7};
        sdb[tid - 84] = __ldg(bp[tid - 84] + c);
    }

    const __half* src = g_x + (size_t)(b * 16 + c) * HW;
#pragma unroll
    for (int j = 0; j < 6; j++) {
        int i = tid + j * 256;
        if (i < 38 * 38) {
            int r = i / 38, cl = i % 38;
            int gy = y0 - 3 + r, gx = x0 - 3 + cl;
            float v = 0.f;
            if ((unsigned)gy < 256u && (unsigned)gx < 256u)
                v = __half2float(__ldg(src + gy * 256 + gx));
            st[r * 39 + cl] = v;
        }
    }
    __syncthreads();

    int ty = tid >> 3;               // 0..31
    int xr = (tid & 7) * 4;          // 0,4,..,28
    size_t pix = (size_t)((b * 16 + c)) * HW + (size_t)(y0 + ty) * 256 + (x0 + xr);

    float o[4];
    dwrun4<1>(st, ty, xr, sdw + 0, sdb[0], o);
    {
        __half2* dst = reinterpret_cast<__half2*>(g_xs + (size_t)0 * BATCH * 16 * HW + pix);
        dst[0] = __halves2half2(__float2half_rn(o[0]), __float2half_rn(o[1]));
        dst[1] = __halves2half2(__float2half_rn(o[2]), __float2half_rn(o[3]));
    }
    dwrun4<3>(st, ty, xr, sdw + 1, sdb[1], o);
    {
        __half2* dst = reinterpret_cast<__half2*>(g_xs + (size_t)1 * BATCH * 16 * HW + pix);
        dst[0] = __halves2half2(__float2half_rn(o[0]), __float2half_rn(o[1]));
        dst[1] = __halves2half2(__float2half_rn(o[2]), __float2half_rn(o[3]));
    }
    dwrun4<5>(st, ty, xr, sdw + 10, sdb[2], o);
    {
        __half2* dst = reinterpret_cast<__half2*>(g_xs + (size_t)2 * BATCH * 16 * HW + pix);
        dst[0] = __halves2half2(__float2half_rn(o[0]), __float2half_rn(o[1]));
        dst[1] = __halves2half2(__float2half_rn(o[2]), __float2half_rn(o[3]));
    }
    dwrun4<7>(st, ty, xr, sdw + 35, sdb[3], o);
    {
        __half2* dst = reinterpret_cast<__half2*>(g_xs + (size_t)3 * BATCH * 16 * HW + pix);
        dst[0] = __halves2half2(__float2half_rn(o[0]), __float2half_rn(o[1]));
        dst[1] = __halves2half2(__float2half_rn(o[2]), __float2half_rn(o[3]));
    }
}

// ---------------------------------------------------------------------------
// K3: fused tail, tile 32x16, 512 threads, scalar fp32 math, channel
// register-prefetch pipeline + DOUBLE-BUFFERED smem (1 barrier/round,
// STS overlapped with compute).
// ---------------------------------------------------------------------------
__device__ __forceinline__ void ce(float& a, float& b) {
    float lo = fminf(a, b);
    float hi = fmaxf(a, b);
    a = lo; b = hi;
}

template <int S, int C>
__device__ __forceinline__ float branch_val(const float* __restrict__ sx, int ty,
                                            int tx, const float* __restrict__ wB) {
    const float* ctr = sx + (ty + S) * C + (tx + S);
    float xc = ctr[0];
    float T[8];
    T[0] = xc - ctr[-S * C - S];
    T[1] = xc - ctr[-S * C];
    T[2] = xc - ctr[-S * C + S];
    T[3] = xc - ctr[S];
    T[4] = xc - ctr[S * C + S];
    T[5] = xc - ctr[S * C];
    T[6] = xc - ctr[S * C - S];
    T[7] = xc - ctr[-S];
    float Sv[4];
#pragma unroll
    for (int k = 0; k < 4; k++) Sv[k] = T[k] + T[k + 4];

    float w10 = wB[0], w11 = wB[1], w12 = wB[2], w13x2 = wB[3], b1 = wB[4];
    float base[4];
#pragma unroll
    for (int j = 0; j < 4; j++) {
        float o = fmaf(w10, Sv[(j + 1) & 3], b1);
        o = fmaf(w11, Sv[(j + 3) & 3], o);
        base[j] = fmaf(w12, Sv[(j + 2) & 3], o);
    }
    float v[8];
#pragma unroll
    for (int k = 0; k < 8; k++)
        v[k] = fmaf(w13x2, T[(k + 4) & 7], base[k & 3]) * T[k];  // wB[3] pre-doubled

    // Batcher odd-even mergesort, 8 elems, 19 CEs, ascending
    ce(v[0], v[1]); ce(v[2], v[3]); ce(v[0], v[2]); ce(v[1], v[3]); ce(v[1], v[2]);
    ce(v[4], v[5]); ce(v[6], v[7]); ce(v[4], v[6]); ce(v[5], v[7]); ce(v[5], v[6]);
    ce(v[0], v[4]); ce(v[1], v[5]); ce(v[2], v[6]); ce(v[3], v[7]);
    ce(v[2], v[4]); ce(v[3], v[5]);
    ce(v[1], v[2]); ce(v[3], v[4]); ce(v[5], v[6]);

    float r = wB[13];
#pragma unroll
    for (int j = 0; j < 8; j++) r = fmaf(v[j], wB[5 + j], r);
    return r;
}

template <int S, int NR>
__device__ __forceinline__ void m_prefetch(float r[NR], const __half* __restrict__ src,
                                           int y0, int x0, int tid) {
    constexpr int R = 16 + 2 * S, C = 32 + 2 * S;
#pragma unroll
    for (int j = 0; j < NR; j++) {
        int i = tid + j * 512;
        float v = 0.f;
        if (i < R * C) {
            int rr = i / C, cl = i % C;
            int gy = y0 - S + rr, gx = x0 - S + cl;
            if ((unsigned)gy < 256u && (unsigned)gx < 256u)
                v = __half2float(__ldg(src + gy * 256 + gx));
        }
        r[j] = v;
    }
}

template <int S, int NR>
__device__ __forceinline__ void m_commit(const float r[NR], float* __restrict__ dst,
                                         int tid) {
    constexpr int R = 16 + 2 * S, C = 32 + 2 * S;
#pragma unroll
    for (int j = 0; j < NR; j++) {
        int i = tid + j * 512;
        if (i < R * C) dst[i] = r[j];
    }
}

#define RBUF 3920   // one buffer: S1@0(612), S3@612(836), S5@1448(1092), S7@2540(1380)

__global__ __launch_bounds__(512) void k_main(
    const float* __restrict__ l1_w, const float* __restrict__ l1_b,
    const float* __restrict__ l2_w, const float* __restrict__ l2_b,
    const float* __restrict__ base_w, const float* __restrict__ bn_scale,
    const float* __restrict__ bn_bias, const float* __restrict__ final_w,
    const float* __restrict__ final_b, float* __restrict__ out) {
    __shared__ float sxt[2 * RBUF];      // double buffer
    __shared__ float swB[4 * 16 * 14];   // per branch/channel: w1[4],b1,w2[8],b2
    __shared__ float sbase[64];
    __shared__ float sbnS[16], sbnB[16], sfw[16];

    int tid = threadIdx.x;
    for (int i = tid; i < 896; i += 512) {
        int e = i % 14;
        int rest = i / 14;
        int cc = rest % 16, br = rest / 16;
        float v;
        if (e < 4) { v = l1_w[(br * 16 + cc) * 4 + e]; if (e == 3) v *= 2.f; }
        else if (e == 4) v = l1_b[br * 16 + cc];
        else if (e < 13) v = l2_w[(br * 16 + cc) * 8 + (e - 5)];
        else v = l2_b[br * 16 + cc];
        swB[i] = v;
    }
    if (tid < 64) sbase[tid] = base_w[tid];
    if (tid < 16) { sbnS[tid] = bn_scale[tid]; sbnB[tid] = bn_bias[tid]; sfw[tid] = final_w[tid]; }

    int tx = tid & 31, ty = tid >> 5;     // ty 0..15
    int x0 = blockIdx.x * 32, y0 = blockIdx.y * 16;
    int b = blockIdx.z;
    float acc = __ldg(final_b);

    const __half* s1 = g_xs + (size_t)((0 * BATCH + b) * 16) * HW;
    const __half* s3 = g_xs + (size_t)((1 * BATCH + b) * 16) * HW;
    const __half* s5 = g_xs + (size_t)((2 * BATCH + b) * 16) * HW;
    const __half* s7 = g_xs + (size_t)((3 * BATCH + b) * 16) * HW;

    float r1[2], r3[2], r5[3], r7[3];
    // Prologue: load c0, commit to buf0, load c1, barrier.
    m_prefetch<1, 2>(r1, s1, y0, x0, tid);
    m_prefetch<3, 2>(r3, s3, y0, x0, tid);
    m_prefetch<5, 3>(r5, s5, y0, x0, tid);
    m_prefetch<7, 3>(r7, s7, y0, x0, tid);
    m_commit<1, 2>(r1, sxt + 0,    tid);
    m_commit<3, 2>(r3, sxt + 612,  tid);
    m_commit<5, 3>(r5, sxt + 1448, tid);
    m_commit<7, 3>(r7, sxt + 2540, tid);
    m_prefetch<1, 2>(r1, s1 + HW, y0, x0, tid);
    m_prefetch<3, 2>(r3, s3 + HW, y0, x0, tid);
    m_prefetch<5, 3>(r5, s5 + HW, y0, x0, tid);
    m_prefetch<7, 3>(r7, s7 + HW, y0, x0, tid);
    __syncthreads();

#pragma unroll 1
    for (int c = 0; c < 16; c++) {
        const float* rd = sxt + (c & 1) * RBUF;
        float* wr = sxt + ((c + 1) & 1) * RBUF;

        // Commit regs (channel c+1) into the other buffer; STS overlaps compute.
        if (c < 15) {
            m_commit<1, 2>(r1, wr + 0,    tid);
            m_commit<3, 2>(r3, wr + 612,  tid);
            m_commit<5, 3>(r5, wr + 1448, tid);
            m_commit<7, 3>(r7, wr + 2540, tid);
        }
        // Issue loads for channel c+2; they fly during compute.
        if (c < 14) {
            size_t off = (size_t)(c + 2) * HW;
            m_prefetch<1, 2>(r1, s1 + off, y0, x0, tid);
            m_prefetch<3, 2>(r3, s3 + off, y0, x0, tid);
            m_prefetch<5, 3>(r5, s5 + off, y0, x0, tid);
            m_prefetch<7, 3>(r7, s7 + off, y0, x0, tid);
        }

        float bv0 = branch_val<1, 34>(rd + 0,    ty, tx, swB + (0 * 16 + c) * 14);
        float bv1 = branch_val<3, 38>(rd + 612,  ty, tx, swB + (1 * 16 + c) * 14);
        float bv2 = branch_val<5, 42>(rd + 1448, ty, tx, swB + (2 * 16 + c) * 14);
        float bv3 = branch_val<7, 46>(rd + 2540, ty, tx, swB + (3 * 16 + c) * 14);

        // sort4 ascending
        ce(bv0, bv1); ce(bv2, bv3); ce(bv0, bv2); ce(bv1, bv3); ce(bv1, bv2);

        float y = bv0 * sbase[c * 4 + 0];
        y = fmaf(bv1, sbase[c * 4 + 1], y);
        y = fmaf(bv2, sbase[c * 4 + 2], y);
        y = fmaf(bv3, sbase[c * 4 + 3], y);
        float t = fmaf(y, sbnS[c], sbnB[c]);
        float si = __fdividef(t, 1.f + __expf(-t));          // SiLU (fast)
        acc = fmaf(si, sfw[c], acc);

        __syncthreads();   // one barrier per round
    }
    out[(size_t)b * HW + (size_t)(y0 + ty) * 256 + (x0 + tx)] =
        __fdividef(1.f, 1.f + __expf(-acc));
}

// ---------------------------------------------------------------------------
extern "C" void kernel_launch(void* const* d_in, const int* in_sizes, int n_in,
                              void* d_out, int out_size) {
    (void)in_sizes; (void)n_in; (void)out_size;
    const ull* cen = (const ull*)d_in[0];
    // d_in[1] = mas (unused by the reference computation)
    const float* in_w = (const float*)d_in[2];
    const float* in_b = (const float*)d_in[3];

    k_inconv<<<1024, 256>>>(cen, in_w, in_b);

    dim3 g2(8, 8, 128);   // W/32, H/32, B*C
    k_dw<<<g2, 256>>>((const float*)d_in[4],  (const float*)d_in[5],
                      (const float*)d_in[6],  (const float*)d_in[7],
                      (const float*)d_in[8],  (const float*)d_in[9],
                      (const float*)d_in[10], (const float*)d_in[11]);

    dim3 g3(8, 16, 8);   // W/32, H/16, B
    k_main<<<g3, 512>>>((const float*)d_in[12], (const float*)d_in[13],
                        (const float*)d_in[14], (const float*)d_in[15],
                        (const float*)d_in[16], (const float*)d_in[17],
                        (const float*)d_in[18], (const float*)d_in[19],
                        (const float*)d_in[20], (float*)d_out);
}

// round 17
// speedup vs baseline: 1.4213x; 1.0316x over previous
#include <cuda_runtime.h>
#include <cuda_fp16.h>

#define HH 256
#define WW 256
#define BATCH 8
#define HW 65536

typedef unsigned long long ull;

// Scratch (allocation-free rule: __device__ globals)
__device__ __half g_x[BATCH * 16 * HW];          // in_conv output  (16.7 MB, fp16)
__device__ __half g_xs[4 * BATCH * 16 * HW];     // dwconv outputs  (67 MB, fp16)

// ---------------- packed f32x2 helpers (sm_100+) ----------------
__device__ __forceinline__ ull pk2(float lo, float hi) {
    ull r;
    asm("mov.b64 %0, {%1, %2};" : "=l"(r) : "r"(__float_as_uint(lo)), "r"(__float_as_uint(hi)));
    return r;
}
__device__ __forceinline__ void upk2(ull v, float& lo, float& hi) {
    unsigned a, b;
    asm("mov.b64 {%0, %1}, %2;" : "=r"(a), "=r"(b) : "l"(v));
    lo = __uint_as_float(a); hi = __uint_as_float(b);
}
__device__ __forceinline__ ull fma2(ull a, ull b, ull c) {
    ull d; asm("fma.rn.f32x2 %0, %1, %2, %3;" : "=l"(d) : "l"(a), "l"(b), "l"(c)); return d;
}

// ---------------------------------------------------------------------------
// K1: 1x1 in_conv 64 -> 16, packed f32x2 FFMA2 (2 px / thread), fp16 out
// ---------------------------------------------------------------------------
__global__ __launch_bounds__(256, 3) void k_inconv(const ull* __restrict__ cen2,
                                                   const float* __restrict__ w,
                                                   const float* __restrict__ bias) {
    __shared__ ull sw[1024];     // {w,w} packed
    __shared__ ull sb[16];
    for (int i = threadIdx.x; i < 1024; i += 256) { float v = w[i]; sw[i] = pk2(v, v); }
    if (threadIdx.x < 16) { float v = bias[threadIdx.x]; sb[threadIdx.x] = pk2(v, v); }
    __syncthreads();

    int idx = blockIdx.x * 256 + threadIdx.x;   // 0 .. 262143  (b, p2)
    int b = idx >> 15;
    int p2 = idx & 32767;
    const ull* cp = cen2 + (size_t)(b * 64) * 32768 + p2;

    ull acc[16];
#pragma unroll
    for (int o = 0; o < 16; o++) acc[o] = sb[o];

#pragma unroll 8
    for (int i = 0; i < 64; i++) {
        ull v = __ldg(cp + (size_t)i * 32768);
#pragma unroll
        for (int o = 0; o < 16; o++) acc[o] = fma2(v, sw[o * 64 + i], acc[o]);
    }
    __half2* xp = reinterpret_cast<__half2*>(g_x) + (size_t)(b * 16) * 32768 + p2;
#pragma unroll
    for (int o = 0; o < 16; o++) {
        float lo, hi; upk2(acc[o], lo, hi);
        xp[(size_t)o * 32768] = __halves2half2(__float2half_rn(lo), __float2half_rn(hi));
    }
}

// ---------------------------------------------------------------------------
// K2 (channel-parallel): one block = one (b, c), tile 32x32, 256 threads,
// 4-px x-run per thread for all 4 kernel sizes, ONE barrier, fp16 in/out.
// ---------------------------------------------------------------------------
template <int S>
__device__ __forceinline__ void dwrun4(const float* __restrict__ st, int ty, int xr,
                                       const float* __restrict__ wk, float bias,
                                       float o[4]) {
    constexpr int P = S / 2;
    o[0] = bias; o[1] = bias; o[2] = bias; o[3] = bias;
#pragma unroll
    for (int kh = 0; kh < S; kh++) {
        const float* row = st + (ty + 3 - P + kh) * 39 + (xr + 3 - P);
        float v[S + 3];
#pragma unroll
        for (int j = 0; j < S + 3; j++) v[j] = row[j];
#pragma unroll
        for (int kw = 0; kw < S; kw++) {
            float wv = wk[kh * S + kw];
            o[0] = fmaf(wv, v[kw + 0], o[0]);
            o[1] = fmaf(wv, v[kw + 1], o[1]);
            o[2] = fmaf(wv, v[kw + 2], o[2]);
            o[3] = fmaf(wv, v[kw + 3], o[3]);
        }
    }
}

__global__ __launch_bounds__(256) void k_dw(
    const float* __restrict__ w1, const float* __restrict__ b1,
    const float* __restrict__ w3, const float* __restrict__ b3,
    const float* __restrict__ w5, const float* __restrict__ b5,
    const float* __restrict__ w7, const float* __restrict__ b7) {
    __shared__ float st[38 * 39];    // 32x32 tile + halo 3, stride 39
    __shared__ float sdw[84];        // this channel's weights: w1@0,w3@1,w5@10,w7@35
    __shared__ float sdb[4];

    int tid = threadIdx.x;
    int bc = blockIdx.z;             // b*16 + c
    int b = bc >> 4, c = bc & 15;
    int y0 = blockIdx.y * 32, x0 = blockIdx.x * 32;

    if (tid == 0)  sdw[0] = __ldg(w1 + c);
    else if (tid < 10)  sdw[tid] = __ldg(w3 + c * 9  + tid - 1);
    else if (tid < 35)  sdw[tid] = __ldg(w5 + c * 25 + tid - 10);
    else if (tid < 84)  sdw[tid] = __ldg(w7 + c * 49 + tid - 35);
    else if (tid < 88) {
        const float* bp[4] = {b1, b3, b5, b7};
        sdb[tid - 84] = __ldg(bp[tid - 84] + c);
    }

    const __half* src = g_x + (size_t)(b * 16 + c) * HW;
#pragma unroll
    for (int j = 0; j < 6; j++) {
        int i = tid + j * 256;
        if (i < 38 * 38) {
            int r = i / 38, cl = i % 38;
            int gy = y0 - 3 + r, gx = x0 - 3 + cl;
            float v = 0.f;
            if ((unsigned)gy < 256u && (unsigned)gx < 256u)
                v = __half2float(__ldg(src + gy * 256 + gx));
            st[r * 39 + cl] = v;
        }
    }
    __syncthreads();

    int ty = tid >> 3;               // 0..31
    int xr = (tid & 7) * 4;          // 0,4,..,28
    size_t pix = (size_t)((b * 16 + c)) * HW + (size_t)(y0 + ty) * 256 + (x0 + xr);

    float o[4];
    dwrun4<1>(st, ty, xr, sdw + 0, sdb[0], o);
    {
        __half2* dst = reinterpret_cast<__half2*>(g_xs + (size_t)0 * BATCH * 16 * HW + pix);
        dst[0] = __halves2half2(__float2half_rn(o[0]), __float2half_rn(o[1]));
        dst[1] = __halves2half2(__float2half_rn(o[2]), __float2half_rn(o[3]));
    }
    dwrun4<3>(st, ty, xr, sdw + 1, sdb[1], o);
    {
        __half2* dst = reinterpret_cast<__half2*>(g_xs + (size_t)1 * BATCH * 16 * HW + pix);
        dst[0] = __halves2half2(__float2half_rn(o[0]), __float2half_rn(o[1]));
        dst[1] = __halves2half2(__float2half_rn(o[2]), __float2half_rn(o[3]));
    }
    dwrun4<5>(st, ty, xr, sdw + 10, sdb[2], o);
    {
        __half2* dst = reinterpret_cast<__half2*>(g_xs + (size_t)2 * BATCH * 16 * HW + pix);
        dst[0] = __halves2half2(__float2half_rn(o[0]), __float2half_rn(o[1]));
        dst[1] = __halves2half2(__float2half_rn(o[2]), __float2half_rn(o[3]));
    }
    dwrun4<7>(st, ty, xr, sdw + 35, sdb[3], o);
    {
        __half2* dst = reinterpret_cast<__half2*>(g_xs + (size_t)3 * BATCH * 16 * HW + pix);
        dst[0] = __halves2half2(__float2half_rn(o[0]), __float2half_rn(o[1]));
        dst[1] = __halves2half2(__float2half_rn(o[2]), __float2half_rn(o[3]));
    }
}

// ---------------------------------------------------------------------------
// K3: fused tail, tile 32x16, 256 threads, 2 px (x-pair)/thread.
// fp32 T/Sv/base/v; HALF2-PACKED sort8 + contraction (2 px per instruction);
// double-buffered smem, channel register-prefetch pipeline.
// ---------------------------------------------------------------------------
__device__ __forceinline__ void ce(float& a, float& b) {
    float lo = fminf(a, b);
    float hi = fmaxf(a, b);
    a = lo; b = hi;
}
__device__ __forceinline__ void ceh(__half2& a, __half2& b) {
    __half2 lo = __hmin2(a, b);
    __half2 hi = __hmax2(a, b);
    a = lo; b = hi;
}

// Packed (2 px) branch value. wB: l1 weights (w10,w11,w12,2*w13,b1) fp32.
// wh: 9 half2 {w2[0..7], b2} each packed {w,w}.
template <int S, int C>
__device__ __forceinline__ void branch_val2h(const float* __restrict__ sx, int ty,
                                             int tx2, const float* __restrict__ wB,
                                             const __half2* __restrict__ wh,
                                             float& ra, float& rb) {
    const float* ctr = sx + (ty + S) * C + (2 * tx2 + S);
    float xcA = ctr[0], xcB = ctr[1];
    const int offs[8] = {-S * C - S, -S * C, -S * C + S, S,
                         S * C + S, S * C, S * C - S, -S};
    float TA[8], TB[8];
#pragma unroll
    for (int j = 0; j < 8; j++) {
        TA[j] = xcA - ctr[offs[j]];
        TB[j] = xcB - ctr[offs[j] + 1];
    }
    float SvA[4], SvB[4];
#pragma unroll
    for (int k = 0; k < 4; k++) { SvA[k] = TA[k] + TA[k + 4]; SvB[k] = TB[k] + TB[k + 4]; }

    float w10 = wB[0], w11 = wB[1], w12 = wB[2], w13x2 = wB[3], b1 = wB[4];
    float baseA[4], baseB[4];
#pragma unroll
    for (int j = 0; j < 4; j++) {
        float oA = fmaf(w10, SvA[(j + 1) & 3], b1);
        float oB = fmaf(w10, SvB[(j + 1) & 3], b1);
        oA = fmaf(w11, SvA[(j + 3) & 3], oA);
        oB = fmaf(w11, SvB[(j + 3) & 3], oB);
        baseA[j] = fmaf(w12, SvA[(j + 2) & 3], oA);
        baseB[j] = fmaf(w12, SvB[(j + 2) & 3], oB);
    }
    __half2 hv[8];
#pragma unroll
    for (int k = 0; k < 8; k++) {
        float vA = fmaf(w13x2, TA[(k + 4) & 7], baseA[k & 3]) * TA[k];
        float vB = fmaf(w13x2, TB[(k + 4) & 7], baseB[k & 3]) * TB[k];
        hv[k] = __floats2half2_rn(vA, vB);
    }
    // Batcher odd-even mergesort, 19 CEs, packed over both pixels
    ceh(hv[0], hv[1]); ceh(hv[2], hv[3]); ceh(hv[0], hv[2]); ceh(hv[1], hv[3]); ceh(hv[1], hv[2]);
    ceh(hv[4], hv[5]); ceh(hv[6], hv[7]); ceh(hv[4], hv[6]); ceh(hv[5], hv[7]); ceh(hv[5], hv[6]);
    ceh(hv[0], hv[4]); ceh(hv[1], hv[5]); ceh(hv[2], hv[6]); ceh(hv[3], hv[7]);
    ceh(hv[2], hv[4]); ceh(hv[3], hv[5]);
    ceh(hv[1], hv[2]); ceh(hv[3], hv[4]); ceh(hv[5], hv[6]);

    __half2 r = wh[8];
#pragma unroll
    for (int j = 0; j < 8; j++) r = __hfma2(hv[j], wh[j], r);
    float2 f = __half22float2(r);
    ra = f.x; rb = f.y;
}

template <int S, int NR>
__device__ __forceinline__ void m_prefetch(float r[NR], const __half* __restrict__ src,
                                           int y0, int x0, int tid) {
    constexpr int R = 16 + 2 * S, C = 32 + 2 * S;
#pragma unroll
    for (int j = 0; j < NR; j++) {
        int i = tid + j * 256;
        float v = 0.f;
        if (i < R * C) {
            int rr = i / C, cl = i % C;
            int gy = y0 - S + rr, gx = x0 - S + cl;
            if ((unsigned)gy < 256u && (unsigned)gx < 256u)
                v = __half2float(__ldg(src + gy * 256 + gx));
        }
        r[j] = v;
    }
}

template <int S, int NR>
__device__ __forceinline__ void m_commit(const float r[NR], float* __restrict__ dst,
                                         int tid) {
    constexpr int R = 16 + 2 * S, C = 32 + 2 * S;
#pragma unroll
    for (int j = 0; j < NR; j++) {
        int i = tid + j * 256;
        if (i < R * C) dst[i] = r[j];
    }
}

#define RBUF 3920   // one buffer: S1@0(612), S3@612(836), S5@1448(1092), S7@2540(1380)

__global__ __launch_bounds__(256) void k_main(
    const float* __restrict__ l1_w, const float* __restrict__ l1_b,
    const float* __restrict__ l2_w, const float* __restrict__ l2_b,
    const float* __restrict__ base_w, const float* __restrict__ bn_scale,
    const float* __restrict__ bn_bias, const float* __restrict__ final_w,
    const float* __restrict__ final_b, float* __restrict__ out) {
    __shared__ float sxt[2 * RBUF];      // double buffer (31.4 KB)
    __shared__ float swB1[4 * 16 * 5];   // l1: w10,w11,w12,2*w13,b1 per (br,c)
    __shared__ __half2 swH[4 * 16 * 9];  // l2: w2[8]+b2 packed {w,w} per (br,c)
    __shared__ float sbase[64];
    __shared__ float sbnS[16], sbnB[16], sfw[16];

    int tid = threadIdx.x;
    for (int i = tid; i < 320; i += 256) {
        int br = i / 80, c = (i / 5) & 15, e = i % 5;
        float v = (e < 4) ? l1_w[(br * 16 + c) * 4 + e] : l1_b[br * 16 + c];
        if (e == 3) v *= 2.f;
        swB1[i] = v;
    }
    for (int i = tid; i < 576; i += 256) {
        int br = i / 144, c = (i / 9) & 15, e = i % 9;
        float v = (e < 8) ? l2_w[(br * 16 + c) * 8 + e] : l2_b[br * 16 + c];
        swH[i] = __floats2half2_rn(v, v);
    }
    if (tid < 64) sbase[tid] = base_w[tid];
    if (tid < 16) { sbnS[tid] = bn_scale[tid]; sbnB[tid] = bn_bias[tid]; sfw[tid] = final_w[tid]; }

    int tx2 = tid & 15, ty = tid >> 4;    // x-pair 0..15, row 0..15
    int x0 = blockIdx.x * 32, y0 = blockIdx.y * 16;
    int b = blockIdx.z;
    float fb = __ldg(final_b);
    float acc0 = fb, acc1 = fb;

    const __half* s1 = g_xs + (size_t)((0 * BATCH + b) * 16) * HW;
    const __half* s3 = g_xs + (size_t)((1 * BATCH + b) * 16) * HW;
    const __half* s5 = g_xs + (size_t)((2 * BATCH + b) * 16) * HW;
    const __half* s7 = g_xs + (size_t)((3 * BATCH + b) * 16) * HW;

    float r1[3], r3[4], r5[5], r7[6];
    // Prologue: load c0, commit to buf0, load c1, barrier.
    m_prefetch<1, 3>(r1, s1, y0, x0, tid);
    m_prefetch<3, 4>(r3, s3, y0, x0, tid);
    m_prefetch<5, 5>(r5, s5, y0, x0, tid);
    m_prefetch<7, 6>(r7, s7, y0, x0, tid);
    m_commit<1, 3>(r1, sxt + 0,    tid);
    m_commit<3, 4>(r3, sxt + 612,  tid);
    m_commit<5, 5>(r5, sxt + 1448, tid);
    m_commit<7, 6>(r7, sxt + 2540, tid);
    m_prefetch<1, 3>(r1, s1 + HW, y0, x0, tid);
    m_prefetch<3, 4>(r3, s3 + HW, y0, x0, tid);
    m_prefetch<5, 5>(r5, s5 + HW, y0, x0, tid);
    m_prefetch<7, 6>(r7, s7 + HW, y0, x0, tid);
    __syncthreads();

#pragma unroll 1
    for (int c = 0; c < 16; c++) {
        const float* rd = sxt + (c & 1) * RBUF;
        float* wr = sxt + ((c + 1) & 1) * RBUF;

        // Commit regs (channel c+1) into the other buffer; STS overlaps compute.
        if (c < 15) {
            m_commit<1, 3>(r1, wr + 0,    tid);
            m_commit<3, 4>(r3, wr + 612,  tid);
            m_commit<5, 5>(r5, wr + 1448, tid);
            m_commit<7, 6>(r7, wr + 2540, tid);
        }
        // Issue loads for channel c+2; they fly during compute.
        if (c < 14) {
            size_t off = (size_t)(c + 2) * HW;
            m_prefetch<1, 3>(r1, s1 + off, y0, x0, tid);
            m_prefetch<3, 4>(r3, s3 + off, y0, x0, tid);
            m_prefetch<5, 5>(r5, s5 + off, y0, x0, tid);
            m_prefetch<7, 6>(r7, s7 + off, y0, x0, tid);
        }

        float bva[4], bvb[4];
        branch_val2h<1, 34>(rd + 0,    ty, tx2, swB1 + (0 * 16 + c) * 5, swH + (0 * 16 + c) * 9, bva[0], bvb[0]);
        branch_val2h<3, 38>(rd + 612,  ty, tx2, swB1 + (1 * 16 + c) * 5, swH + (1 * 16 + c) * 9, bva[1], bvb[1]);
        branch_val2h<5, 42>(rd + 1448, ty, tx2, swB1 + (2 * 16 + c) * 5, swH + (2 * 16 + c) * 9, bva[2], bvb[2]);
        branch_val2h<7, 46>(rd + 2540, ty, tx2, swB1 + (3 * 16 + c) * 5, swH + (3 * 16 + c) * 9, bva[3], bvb[3]);

        // sort4 ascending per px (fp32)
        ce(bva[0], bva[1]); ce(bva[2], bva[3]); ce(bva[0], bva[2]); ce(bva[1], bva[3]); ce(bva[1], bva[2]);
        ce(bvb[0], bvb[1]); ce(bvb[2], bvb[3]); ce(bvb[0], bvb[2]); ce(bvb[1], bvb[3]); ce(bvb[1], bvb[2]);

        float y0v = bva[0] * sbase[c * 4 + 0];
        y0v = fmaf(bva[1], sbase[c * 4 + 1], y0v);
        y0v = fmaf(bva[2], sbase[c * 4 + 2], y0v);
        y0v = fmaf(bva[3], sbase[c * 4 + 3], y0v);
        float y1v = bvb[0] * sbase[c * 4 + 0];
        y1v = fmaf(bvb[1], sbase[c * 4 + 1], y1v);
        y1v = fmaf(bvb[2], sbase[c * 4 + 2], y1v);
        y1v = fmaf(bvb[3], sbase[c * 4 + 3], y1v);
        float t0 = fmaf(y0v, sbnS[c], sbnB[c]);
        float t1 = fmaf(y1v, sbnS[c], sbnB[c]);
        float si0 = __fdividef(t0, 1.f + __expf(-t0));
        float si1 = __fdividef(t1, 1.f + __expf(-t1));
        acc0 = fmaf(si0, sfw[c], acc0);
        acc1 = fmaf(si1, sfw[c], acc1);

        __syncthreads();   // one barrier per round
    }
    float2 o = make_float2(__fdividef(1.f, 1.f + __expf(-acc0)),
                           __fdividef(1.f, 1.f + __expf(-acc1)));
    *reinterpret_cast<float2*>(out + (size_t)b * HW + (size_t)(y0 + ty) * 256 +
                               (x0 + 2 * tx2)) = o;
}

// ---------------------------------------------------------------------------
extern "C" void kernel_launch(void* const* d_in, const int* in_sizes, int n_in,
                              void* d_out, int out_size) {
    (void)in_sizes; (void)n_in; (void)out_size;
    const ull* cen = (const ull*)d_in[0];
    // d_in[1] = mas (unused by the reference computation)
    const float* in_w = (const float*)d_in[2];
    const float* in_b = (const float*)d_in[3];

    k_inconv<<<1024, 256>>>(cen, in_w, in_b);

    dim3 g2(8, 8, 128);   // W/32, H/32, B*C
    k_dw<<<g2, 256>>>((const float*)d_in[4],  (const float*)d_in[5],
                      (const float*)d_in[6],  (const float*)d_in[7],
                      (const float*)d_in[8],  (const float*)d_in[9],
                      (const float*)d_in[10], (const float*)d_in[11]);

    dim3 g3(8, 16, 8);   // W/32, H/16, B
    k_main<<<g3, 256>>>((const float*)d_in[12], (const float*)d_in[13],
                        (const float*)d_in[14], (const float*)d_in[15],
                        (const float*)d_in[16], (const float*)d_in[17],
                        (const float*)d_in[18], (const float*)d_in[19],
                        (const float*)d_in[20], (float*)d_out);
}